// round 1
// baseline (speedup 1.0000x reference)
#include <cuda_runtime.h>
#include <math.h>

// Problem constants (fixed by the dataset)
#define NNODES   50000
#define FEAT     144        // C_RAD * SH_DIM
#define CRAD     16
#define SHD      9
#define NRBF     128
#define CUTOFF   5.0f
#define TBL      32768      // radial-table resolution

// ---------------- device scratch (no allocs allowed) ----------------
__device__ float g_table[(TBL + 1) * CRAD];   // rad(d) lookup, +1 sentinel row at d>=CUTOFF
__device__ float g_deg[(size_t)NNODES * FEAT]; // scatter accumulator (28.8 MB)

__device__ __forceinline__ float silu_f(float x) {
    return x / (1.0f + expf(-x));
}

// ---------------- kernel 1: build rad(d) table ----------------
// One block per d sample; 128 threads: rbf -> 64 -> 64 -> 16.
__global__ void build_table_kernel(const float* __restrict__ W1, const float* __restrict__ b1,
                                   const float* __restrict__ W2, const float* __restrict__ b2,
                                   const float* __restrict__ W3) {
    __shared__ float s_rbf[NRBF];
    __shared__ float s_h1[64];
    __shared__ float s_h2[64];

    const int i = blockIdx.x;          // 0..TBL
    const int t = threadIdx.x;         // 0..127
    const float d = (float)i * (CUTOFF / (float)TBL);   // exact at i==TBL -> 5.0

    // ExpNormalSmearing constants (constant-folded in double)
    const double startd = 0.006737946999085467;          // exp(-5)
    const double width  = (2.0 / 128.0) * (1.0 - startd);
    const float  BETA   = (float)(1.0 / (width * width));
    const float  mean   = (float)(startd + (1.0 - startd) * ((double)t / 127.0));

    float cut = 0.0f;
    if (d < CUTOFF)
        cut = 0.5f * (cosf(d * (float)(3.14159265358979323846 / 5.0)) + 1.0f);
    const float ex = expf(-d);                // alpha = 5/CUTOFF = 1
    const float dd = ex - mean;
    s_rbf[t] = cut * expf(-BETA * dd * dd);
    __syncthreads();

    if (t < 64) {
        float a = b1[t];
        #pragma unroll 8
        for (int k = 0; k < NRBF; k++) a = fmaf(s_rbf[k], W1[k * 64 + t], a);
        s_h1[t] = silu_f(a);
    }
    __syncthreads();

    if (t < 64) {
        float a = b2[t];
        #pragma unroll 8
        for (int k = 0; k < 64; k++) a = fmaf(s_h1[k], W2[k * 64 + t], a);
        s_h2[t] = silu_f(a);
    }
    __syncthreads();

    if (t < CRAD) {
        float a = 0.0f;
        #pragma unroll 8
        for (int k = 0; k < 64; k++) a = fmaf(s_h2[k], W3[k * CRAD + t], a);
        g_table[i * CRAD + t] = a;
    }
}

// ---------------- zeroing kernels ----------------
__global__ void zero_deg_kernel(int n4) {
    int i = blockIdx.x * blockDim.x + threadIdx.x;
    if (i < n4) reinterpret_cast<float4*>(g_deg)[i] = make_float4(0.f, 0.f, 0.f, 0.f);
}

__global__ void zero_out_kernel(float* __restrict__ out, int n) {
    int i = blockIdx.x * blockDim.x + threadIdx.x;
    if (i < n) out[i] = 0.0f;
}

// ---------------- kernel 2: edge pass ----------------
// One thread per edge: gather pos, SH(l=0..2), table interp for rad[16],
// scatter 144 atomics (skipped when rad == 0, i.e. d >= cutoff with zero biases).
__global__ void __launch_bounds__(256) edge_kernel(const float* __restrict__ pos,
                                                   const int* __restrict__ esrc,
                                                   const int* __restrict__ edst,
                                                   int E) {
    int e = blockIdx.x * blockDim.x + threadIdx.x;
    if (e >= E) return;

    const int s = esrc[e];
    const int d = edst[e];

    const float3 ps = *reinterpret_cast<const float3*>(pos + 3 * (size_t)s);
    const float3 pd = *reinterpret_cast<const float3*>(pos + 3 * (size_t)d);
    const float vx = ps.x - pd.x, vy = ps.y - pd.y, vz = ps.z - pd.z;
    const float len = sqrtf(vx * vx + vy * vy + vz * vz);
    const float inv = 1.0f / fmaxf(len, 1e-12f);
    const float x = vx * inv, y = vy * inv, z = vz * inv;

    const float s3 = 1.7320508075688772f;
    const float s5 = 2.23606797749979f;
    const float s15 = 3.872983346207417f;
    float sh[SHD];
    sh[0] = 1.0f;
    sh[1] = s3 * x; sh[2] = s3 * y; sh[3] = s3 * z;
    sh[4] = s15 * x * z;
    sh[5] = s15 * x * y;
    sh[6] = s5 * (y * y - 0.5f * (x * x + z * z));
    sh[7] = s15 * y * z;
    sh[8] = 0.5f * s15 * (z * z - x * x);

    // table interpolation (sentinel row TBL handles d >= CUTOFF exactly)
    float u = len * ((float)TBL / CUTOFF);
    u = fminf(u, (float)TBL);
    int i0 = min((int)u, TBL - 1);
    float f = u - (float)i0;

    const float4* t0 = reinterpret_cast<const float4*>(g_table + (size_t)i0 * CRAD);
    const float4* t1 = reinterpret_cast<const float4*>(g_table + (size_t)(i0 + 1) * CRAD);
    float rad[CRAD];
    float mx = 0.0f;
    #pragma unroll
    for (int q = 0; q < 4; q++) {
        float4 a = t0[q], b = t1[q];
        rad[4 * q + 0] = fmaf(f, b.x - a.x, a.x);
        rad[4 * q + 1] = fmaf(f, b.y - a.y, a.y);
        rad[4 * q + 2] = fmaf(f, b.z - a.z, a.z);
        rad[4 * q + 3] = fmaf(f, b.w - a.w, a.w);
        mx = fmaxf(mx, fabsf(rad[4 * q + 0]));
        mx = fmaxf(mx, fabsf(rad[4 * q + 1]));
        mx = fmaxf(mx, fabsf(rad[4 * q + 2]));
        mx = fmaxf(mx, fabsf(rad[4 * q + 3]));
    }
    if (mx == 0.0f) return;   // adding exact zeros is a no-op

    float* base = g_deg + (size_t)d * FEAT;
    #pragma unroll
    for (int c = 0; c < CRAD; c++) {
        const float rc = rad[c];
        #pragma unroll
        for (int k = 0; k < SHD; k++) {
            atomicAdd(base + c * SHD + k, rc * sh[k]);
        }
    }
}

// ---------------- kernel 3: node head + graph reduction ----------------
// Block: 288 threads = 8 node-groups x 36 j-groups (4 j each).
// 32 nodes per block; NF tile staged in smem; Wh1 streamed as float4 via L1.
__global__ void __launch_bounds__(288) node_kernel(const float* __restrict__ atab,
                                                   const int* __restrict__ natom,
                                                   const float* __restrict__ Wh1,
                                                   const float* __restrict__ bh1,
                                                   const float* __restrict__ Wh2,
                                                   const float* __restrict__ bh2,
                                                   const int* __restrict__ batch,
                                                   float* __restrict__ out,
                                                   int N) {
    __shared__ float sNF[32][FEAT];

    const float INV_SQRT_DEG = 1.0f / sqrtf(15.57930850982666f);
    const float INV_SQRT_NODES = 1.0f / sqrtf(18.03065905448718f);

    const int t = threadIdx.x;
    const int tx = t % 36;          // j0 = 4*tx
    const int ty = t / 36;          // 0..7
    const int nb = blockIdx.x * 32;

    // stage node features
    for (int idx = t; idx < 32 * FEAT; idx += 288) {
        const int n = idx / FEAT;
        const int k = idx - n * FEAT;
        const int gn = nb + n;
        float v = 0.0f;
        if (gn < N) {
            v = atab[(size_t)natom[gn] * FEAT + k]
              + g_deg[(size_t)gn * FEAT + k] * INV_SQRT_DEG;
        }
        sNF[n][k] = v;
    }
    __syncthreads();

    float acc[4][4];
    #pragma unroll
    for (int a = 0; a < 4; a++)
        #pragma unroll
        for (int b = 0; b < 4; b++) acc[a][b] = 0.0f;

    const int j0 = 4 * tx;
    for (int k = 0; k < FEAT; k++) {
        const float4 w = *reinterpret_cast<const float4*>(Wh1 + (size_t)k * FEAT + j0);
        #pragma unroll
        for (int nn = 0; nn < 4; nn++) {
            const float v = sNF[ty + 8 * nn][k];
            acc[nn][0] = fmaf(v, w.x, acc[nn][0]);
            acc[nn][1] = fmaf(v, w.y, acc[nn][1]);
            acc[nn][2] = fmaf(v, w.z, acc[nn][2]);
            acc[nn][3] = fmaf(v, w.w, acc[nn][3]);
        }
    }

    const float4 b4 = *reinterpret_cast<const float4*>(bh1 + j0);
    const float4 w2 = *reinterpret_cast<const float4*>(Wh2 + j0);
    const float bias2 = bh2[0];

    #pragma unroll
    for (int nn = 0; nn < 4; nn++) {
        const int gn = nb + ty + 8 * nn;
        if (gn >= N) continue;
        float p = silu_f(acc[nn][0] + b4.x) * w2.x
                + silu_f(acc[nn][1] + b4.y) * w2.y
                + silu_f(acc[nn][2] + b4.z) * w2.z
                + silu_f(acc[nn][3] + b4.w) * w2.w;
        if (tx == 0) p += bias2;
        atomicAdd(out + batch[gn], p * INV_SQRT_NODES);
    }
}

// ---------------- launcher ----------------
extern "C" void kernel_launch(void* const* d_in, const int* in_sizes, int n_in,
                              void* d_out, int out_size) {
    const float* pos  = (const float*)d_in[0];
    const float* atab = (const float*)d_in[1];
    const float* W1   = (const float*)d_in[2];
    const float* b1   = (const float*)d_in[3];
    const float* W2   = (const float*)d_in[4];
    const float* b2   = (const float*)d_in[5];
    const float* W3   = (const float*)d_in[6];
    const float* Wh1  = (const float*)d_in[7];
    const float* bh1  = (const float*)d_in[8];
    const float* Wh2  = (const float*)d_in[9];
    const float* bh2  = (const float*)d_in[10];
    const int* natom  = (const int*)d_in[11];
    const int* esrc   = (const int*)d_in[12];
    const int* edst   = (const int*)d_in[13];
    const int* batch  = (const int*)d_in[14];
    float* out = (float*)d_out;

    const int N = in_sizes[11];
    const int E = in_sizes[12];
    const int G = out_size;

    // 1. radial table (independent of deg zeroing)
    build_table_kernel<<<TBL + 1, 128>>>(W1, b1, W2, b2, W3);

    // 2. zero scratch + output
    const int n4 = (N * FEAT) / 4;
    zero_deg_kernel<<<(n4 + 255) / 256, 256>>>(n4);
    zero_out_kernel<<<(G + 255) / 256, 256>>>(out, G);

    // 3. edge scatter
    edge_kernel<<<(E + 255) / 256, 256>>>(pos, esrc, edst, E);

    // 4. node head + graph reduction
    node_kernel<<<(N + 31) / 32, 288>>>(atab, natom, Wh1, bh1, Wh2, bh2, batch, out, N);
}

// round 3
// speedup vs baseline: 1.7761x; 1.7761x over previous
#include <cuda_runtime.h>
#include <math.h>

// Problem constants (fixed by the dataset)
#define NNODES   50000
#define FEAT     144        // C_RAD * SH_DIM
#define CRAD     16
#define SHD      9
#define NRBF     128
#define CUTOFF   5.0f
#define TBL      8192       // radial-table resolution (interp err ~8e-6 rel, gate is 1e-3)

// ---------------- device scratch (no allocs allowed) ----------------
__device__ float g_table[(TBL + 1) * CRAD];    // rad(d) lookup, +1 sentinel row at d>=CUTOFF
__device__ float g_deg[(size_t)NNODES * FEAT]; // scatter accumulator (28.8 MB)

__device__ __forceinline__ float silu_f(float x) {
    return x / (1.0f + expf(-x));
}

// f32x2 packed-FMA helpers (sm_103a; ptxas never auto-fuses these)
__device__ __forceinline__ unsigned long long pk2(float lo, float hi) {
    unsigned long long r;
    asm("mov.b64 %0, {%1, %2};" : "=l"(r) : "f"(lo), "f"(hi));
    return r;
}
__device__ __forceinline__ void fma2(unsigned long long& d,
                                     unsigned long long a, unsigned long long b) {
    asm("fma.rn.f32x2 %0, %1, %2, %0;" : "+l"(d) : "l"(a), "l"(b));
}
__device__ __forceinline__ void unpk2(unsigned long long v, float& lo, float& hi) {
    asm("mov.b64 {%0, %1}, %2;" : "=f"(lo), "=f"(hi) : "l"(v));
}

// ---------------- kernel 1: build rad(d) table ----------------
__global__ void build_table_kernel(const float* __restrict__ W1, const float* __restrict__ b1,
                                   const float* __restrict__ W2, const float* __restrict__ b2,
                                   const float* __restrict__ W3) {
    __shared__ float s_rbf[NRBF];
    __shared__ float s_h1[64];
    __shared__ float s_h2[64];

    const int i = blockIdx.x;          // 0..TBL
    const int t = threadIdx.x;         // 0..127
    const float d = (float)i * (CUTOFF / (float)TBL);   // exact at i==TBL -> 5.0

    const double startd = 0.006737946999085467;          // exp(-5)
    const double width  = (2.0 / 128.0) * (1.0 - startd);
    const float  BETA   = (float)(1.0 / (width * width));
    const float  mean   = (float)(startd + (1.0 - startd) * ((double)t / 127.0));

    float cut = 0.0f;
    if (d < CUTOFF)
        cut = 0.5f * (cosf(d * (float)(3.14159265358979323846 / 5.0)) + 1.0f);
    const float ex = expf(-d);
    const float dd = ex - mean;
    s_rbf[t] = cut * expf(-BETA * dd * dd);
    __syncthreads();

    if (t < 64) {
        float a = b1[t];
        #pragma unroll 8
        for (int k = 0; k < NRBF; k++) a = fmaf(s_rbf[k], W1[k * 64 + t], a);
        s_h1[t] = silu_f(a);
    }
    __syncthreads();

    if (t < 64) {
        float a = b2[t];
        #pragma unroll 8
        for (int k = 0; k < 64; k++) a = fmaf(s_h1[k], W2[k * 64 + t], a);
        s_h2[t] = silu_f(a);
    }
    __syncthreads();

    if (t < CRAD) {
        float a = 0.0f;
        #pragma unroll 8
        for (int k = 0; k < 64; k++) a = fmaf(s_h2[k], W3[k * CRAD + t], a);
        g_table[i * CRAD + t] = a;
    }
}

// ---------------- zeroing kernels ----------------
__global__ void zero_deg_kernel(int n4) {
    int i = blockIdx.x * blockDim.x + threadIdx.x;
    if (i < n4) reinterpret_cast<float4*>(g_deg)[i] = make_float4(0.f, 0.f, 0.f, 0.f);
}

__global__ void zero_out_kernel(float* __restrict__ out, int n) {
    int i = blockIdx.x * blockDim.x + threadIdx.x;
    if (i < n) out[i] = 0.0f;
}

// ---------------- kernel 2: edge pass ----------------
// One thread per edge; 36 x red.global.add.v4.f32 instead of 144 scalar atomics
// (LTS atomic bound is per-operation; 4x fewer LTS transactions).
__global__ void __launch_bounds__(256) edge_kernel(const float* __restrict__ pos,
                                                   const int* __restrict__ esrc,
                                                   const int* __restrict__ edst,
                                                   int E) {
    int e = blockIdx.x * blockDim.x + threadIdx.x;
    if (e >= E) return;

    const int s = esrc[e];
    const int d = edst[e];

    const float3 ps = *reinterpret_cast<const float3*>(pos + 3 * (size_t)s);
    const float3 pd = *reinterpret_cast<const float3*>(pos + 3 * (size_t)d);
    const float vx = ps.x - pd.x, vy = ps.y - pd.y, vz = ps.z - pd.z;
    const float len = sqrtf(vx * vx + vy * vy + vz * vz);
    const float inv = 1.0f / fmaxf(len, 1e-12f);
    const float x = vx * inv, y = vy * inv, z = vz * inv;

    const float s3 = 1.7320508075688772f;
    const float s5 = 2.23606797749979f;
    const float s15 = 3.872983346207417f;
    float sh[SHD];
    sh[0] = 1.0f;
    sh[1] = s3 * x; sh[2] = s3 * y; sh[3] = s3 * z;
    sh[4] = s15 * x * z;
    sh[5] = s15 * x * y;
    sh[6] = s5 * (y * y - 0.5f * (x * x + z * z));
    sh[7] = s15 * y * z;
    sh[8] = 0.5f * s15 * (z * z - x * x);

    // table interpolation (sentinel row TBL handles d >= CUTOFF exactly)
    float u = len * ((float)TBL / CUTOFF);
    u = fminf(u, (float)TBL);
    int i0 = min((int)u, TBL - 1);
    float f = u - (float)i0;

    const float4* t0 = reinterpret_cast<const float4*>(g_table + (size_t)i0 * CRAD);
    const float4* t1 = reinterpret_cast<const float4*>(g_table + (size_t)(i0 + 1) * CRAD);
    float rad[CRAD];
    float mx = 0.0f;
    #pragma unroll
    for (int q = 0; q < 4; q++) {
        float4 a = t0[q], b = t1[q];
        rad[4 * q + 0] = fmaf(f, b.x - a.x, a.x);
        rad[4 * q + 1] = fmaf(f, b.y - a.y, a.y);
        rad[4 * q + 2] = fmaf(f, b.z - a.z, a.z);
        rad[4 * q + 3] = fmaf(f, b.w - a.w, a.w);
        mx = fmaxf(mx, fabsf(rad[4 * q + 0]));
        mx = fmaxf(mx, fabsf(rad[4 * q + 1]));
        mx = fmaxf(mx, fabsf(rad[4 * q + 2]));
        mx = fmaxf(mx, fabsf(rad[4 * q + 3]));
    }
    if (mx == 0.0f) return;   // d >= cutoff with zero biases -> exact zeros

    float* base = g_deg + (size_t)d * FEAT;   // 16B-aligned (144*4 = 576 bytes/row)
    #pragma unroll
    for (int g = 0; g < FEAT / 4; g++) {
        const float e0 = rad[(4 * g + 0) / SHD] * sh[(4 * g + 0) % SHD];
        const float e1 = rad[(4 * g + 1) / SHD] * sh[(4 * g + 1) % SHD];
        const float e2 = rad[(4 * g + 2) / SHD] * sh[(4 * g + 2) % SHD];
        const float e3 = rad[(4 * g + 3) / SHD] * sh[(4 * g + 3) % SHD];
        asm volatile("red.global.add.v4.f32 [%0], {%1, %2, %3, %4};"
                     :: "l"(base + 4 * g), "f"(e0), "f"(e1), "f"(e2), "f"(e3)
                     : "memory");
    }
}

// ---------------- kernel 3: node head + graph reduction ----------------
// Block: 288 threads = 8 node-groups x 36 j-groups (4 j each), f32x2 accumulators.
__global__ void __launch_bounds__(288) node_kernel(const float* __restrict__ atab,
                                                   const int* __restrict__ natom,
                                                   const float* __restrict__ Wh1,
                                                   const float* __restrict__ bh1,
                                                   const float* __restrict__ Wh2,
                                                   const float* __restrict__ bh2,
                                                   const int* __restrict__ batch,
                                                   float* __restrict__ out,
                                                   int N) {
    __shared__ float sNF[32][FEAT];

    const float INV_SQRT_DEG = 1.0f / sqrtf(15.57930850982666f);
    const float INV_SQRT_NODES = 1.0f / sqrtf(18.03065905448718f);

    const int t = threadIdx.x;
    const int tx = t % 36;          // j0 = 4*tx
    const int ty = t / 36;          // 0..7
    const int nb = blockIdx.x * 32;

    // stage node features
    for (int idx = t; idx < 32 * FEAT; idx += 288) {
        const int n = idx / FEAT;
        const int k = idx - n * FEAT;
        const int gn = nb + n;
        float v = 0.0f;
        if (gn < N) {
            v = atab[(size_t)natom[gn] * FEAT + k]
              + g_deg[(size_t)gn * FEAT + k] * INV_SQRT_DEG;
        }
        sNF[n][k] = v;
    }
    __syncthreads();

    unsigned long long acc01[4], acc23[4];
    #pragma unroll
    for (int nn = 0; nn < 4; nn++) { acc01[nn] = 0ULL; acc23[nn] = 0ULL; }

    const int j0 = 4 * tx;
    for (int k = 0; k < FEAT; k++) {
        const float4 w = *reinterpret_cast<const float4*>(Wh1 + (size_t)k * FEAT + j0);
        const unsigned long long w01 = pk2(w.x, w.y);
        const unsigned long long w23 = pk2(w.z, w.w);
        #pragma unroll
        for (int nn = 0; nn < 4; nn++) {
            const float v = sNF[ty + 8 * nn][k];
            const unsigned long long vv = pk2(v, v);
            fma2(acc01[nn], vv, w01);
            fma2(acc23[nn], vv, w23);
        }
    }

    const float4 b4 = *reinterpret_cast<const float4*>(bh1 + j0);
    const float4 w2 = *reinterpret_cast<const float4*>(Wh2 + j0);
    const float bias2 = bh2[0];

    #pragma unroll
    for (int nn = 0; nn < 4; nn++) {
        const int gn = nb + ty + 8 * nn;
        if (gn >= N) continue;
        float a0, a1, a2, a3;
        unpk2(acc01[nn], a0, a1);
        unpk2(acc23[nn], a2, a3);
        float p = silu_f(a0 + b4.x) * w2.x
                + silu_f(a1 + b4.y) * w2.y
                + silu_f(a2 + b4.z) * w2.z
                + silu_f(a3 + b4.w) * w2.w;
        if (tx == 0) p += bias2;
        atomicAdd(out + batch[gn], p * INV_SQRT_NODES);
    }
}

// ---------------- launcher ----------------
extern "C" void kernel_launch(void* const* d_in, const int* in_sizes, int n_in,
                              void* d_out, int out_size) {
    const float* pos  = (const float*)d_in[0];
    const float* atab = (const float*)d_in[1];
    const float* W1   = (const float*)d_in[2];
    const float* b1   = (const float*)d_in[3];
    const float* W2   = (const float*)d_in[4];
    const float* b2   = (const float*)d_in[5];
    const float* W3   = (const float*)d_in[6];
    const float* Wh1  = (const float*)d_in[7];
    const float* bh1  = (const float*)d_in[8];
    const float* Wh2  = (const float*)d_in[9];
    const float* bh2  = (const float*)d_in[10];
    const int* natom  = (const int*)d_in[11];
    const int* esrc   = (const int*)d_in[12];
    const int* edst   = (const int*)d_in[13];
    const int* batch  = (const int*)d_in[14];
    float* out = (float*)d_out;

    const int N = in_sizes[11];
    const int E = in_sizes[12];
    const int G = out_size;

    // 1. radial table
    build_table_kernel<<<TBL + 1, 128>>>(W1, b1, W2, b2, W3);

    // 2. zero scratch + output
    const int n4 = (N * FEAT) / 4;
    zero_deg_kernel<<<(n4 + 255) / 256, 256>>>(n4);
    zero_out_kernel<<<(G + 255) / 256, 256>>>(out, G);

    // 3. edge scatter (v4 reductions)
    edge_kernel<<<(E + 255) / 256, 256>>>(pos, esrc, edst, E);

    // 4. node head + graph reduction
    node_kernel<<<(N + 31) / 32, 288>>>(atab, natom, Wh1, bh1, Wh2, bh2, batch, out, N);
}

// round 4
// speedup vs baseline: 1.9234x; 1.0829x over previous
#include <cuda_runtime.h>
#include <math.h>

// Problem constants (fixed by the dataset)
#define NNODES   50000
#define FEAT     144        // C_RAD * SH_DIM
#define CRAD     16
#define SHD      9
#define NRBF     128
#define CUTOFF   5.0f
#define TBL      8192       // radial-table resolution
#define SLOTS    64         // edge-id bucket slots per node (overflow -> fallback)
#define OVF_CAP  8192

// ---------------- device scratch (no allocs allowed) ----------------
__device__ float g_table[(TBL + 1) * CRAD];     // rad(d) lookup (+ sentinel row)
__device__ float g_deg[(size_t)NNODES * FEAT];  // aggregated, PRE-SCALED by 1/sqrt(deg_avg)
__device__ int   g_cnt[NNODES];                 // per-dst edge count
__device__ int   g_eid[(size_t)NNODES * SLOTS]; // bucketed edge ids
__device__ int   g_ovf[OVF_CAP];                // overflow edge ids
__device__ int   g_ovfcnt;

#define INV_SQRT_DEG   0.25335570773f   // 1/sqrt(15.57930850982666)
#define INV_SQRT_NODES 0.23549661171f   // 1/sqrt(18.03065905448718)

__device__ __forceinline__ float silu_f(float x) {
    return x / (1.0f + expf(-x));
}

// f32x2 packed-FMA helpers (sm_103a)
__device__ __forceinline__ unsigned long long pk2(float lo, float hi) {
    unsigned long long r;
    asm("mov.b64 %0, {%1, %2};" : "=l"(r) : "f"(lo), "f"(hi));
    return r;
}
__device__ __forceinline__ void fma2(unsigned long long& d,
                                     unsigned long long a, unsigned long long b) {
    asm("fma.rn.f32x2 %0, %1, %2, %0;" : "+l"(d) : "l"(a), "l"(b));
}
__device__ __forceinline__ void unpk2(unsigned long long v, float& lo, float& hi) {
    asm("mov.b64 {%0, %1}, %2;" : "=f"(lo), "=f"(hi) : "l"(v));
}

// per-edge geometry: rad[16] (table interp) + sh[9]
__device__ __forceinline__ void edge_geom(float vx, float vy, float vz,
                                          float* rad, float* sh) {
    const float len = sqrtf(vx * vx + vy * vy + vz * vz);
    const float inv = 1.0f / fmaxf(len, 1e-12f);
    const float x = vx * inv, y = vy * inv, z = vz * inv;

    const float s3 = 1.7320508075688772f;
    const float s5 = 2.23606797749979f;
    const float s15 = 3.872983346207417f;
    sh[0] = 1.0f;
    sh[1] = s3 * x; sh[2] = s3 * y; sh[3] = s3 * z;
    sh[4] = s15 * x * z;
    sh[5] = s15 * x * y;
    sh[6] = s5 * (y * y - 0.5f * (x * x + z * z));
    sh[7] = s15 * y * z;
    sh[8] = 0.5f * s15 * (z * z - x * x);

    float u = len * ((float)TBL / CUTOFF);
    u = fminf(u, (float)TBL);
    int i0 = min((int)u, TBL - 1);
    float f = u - (float)i0;
    const float4* t0 = reinterpret_cast<const float4*>(g_table + (size_t)i0 * CRAD);
    const float4* t1 = reinterpret_cast<const float4*>(g_table + (size_t)(i0 + 1) * CRAD);
    #pragma unroll
    for (int q = 0; q < 4; q++) {
        float4 a = t0[q], b = t1[q];
        rad[4 * q + 0] = fmaf(f, b.x - a.x, a.x);
        rad[4 * q + 1] = fmaf(f, b.y - a.y, a.y);
        rad[4 * q + 2] = fmaf(f, b.z - a.z, a.z);
        rad[4 * q + 3] = fmaf(f, b.w - a.w, a.w);
    }
}

// ---------------- kernel A: zero counters + output ----------------
__global__ void zero_kernel(float* __restrict__ out, int G) {
    int i = blockIdx.x * blockDim.x + threadIdx.x;
    if (i < NNODES) g_cnt[i] = 0;
    if (i < G) out[i] = 0.0f;
    if (i == 0) g_ovfcnt = 0;
}

// ---------------- kernel B (fat): radial table + edge-id bucketing ----------------
// Blocks [0, TBL+1): build table.  Blocks [TBL+1, ...): scatter edge ids.
__global__ void __launch_bounds__(256) fat_kernel(const float* __restrict__ W1, const float* __restrict__ b1,
                                                  const float* __restrict__ W2, const float* __restrict__ b2,
                                                  const float* __restrict__ W3,
                                                  const int* __restrict__ edst, int E) {
    if (blockIdx.x < TBL + 1) {
        __shared__ float s_rbf[NRBF];
        __shared__ float s_h1[64];
        __shared__ float s_h2[64];

        const int i = blockIdx.x;
        const int t = threadIdx.x;
        const float d = (float)i * (CUTOFF / (float)TBL);

        const double startd = 0.006737946999085467;          // exp(-5)
        const double width  = (2.0 / 128.0) * (1.0 - startd);
        const float  BETA   = (float)(1.0 / (width * width));

        if (t < NRBF) {
            const float mean = (float)(startd + (1.0 - startd) * ((double)t / 127.0));
            float cut = 0.0f;
            if (d < CUTOFF)
                cut = 0.5f * (cosf(d * (float)(3.14159265358979323846 / 5.0)) + 1.0f);
            const float ex = expf(-d);
            const float dd = ex - mean;
            s_rbf[t] = cut * expf(-BETA * dd * dd);
        }
        __syncthreads();

        if (t < 64) {
            float a = b1[t];
            #pragma unroll 8
            for (int k = 0; k < NRBF; k++) a = fmaf(s_rbf[k], W1[k * 64 + t], a);
            s_h1[t] = silu_f(a);
        }
        __syncthreads();
        if (t < 64) {
            float a = b2[t];
            #pragma unroll 8
            for (int k = 0; k < 64; k++) a = fmaf(s_h1[k], W2[k * 64 + t], a);
            s_h2[t] = silu_f(a);
        }
        __syncthreads();
        if (t < CRAD) {
            float a = 0.0f;
            #pragma unroll 8
            for (int k = 0; k < 64; k++) a = fmaf(s_h2[k], W3[k * CRAD + t], a);
            g_table[i * CRAD + t] = a;
        }
    } else {
        const int e = (blockIdx.x - (TBL + 1)) * 256 + threadIdx.x;
        if (e < E) {
            const int d = edst[e];
            const int pos = atomicAdd(&g_cnt[d], 1);
            if (pos < SLOTS) {
                g_eid[(size_t)d * SLOTS + pos] = e;
            } else {
                const int oi = atomicAdd(&g_ovfcnt, 1);
                if (oi < OVF_CAP) g_ovf[oi] = e;
            }
        }
    }
}

// ---------------- kernel C: warp-per-node gather ----------------
// Lane mapping: lane = 2*c + h; c in [0,16), h in {0,1}. Lane owns outputs
// j = 9*c + k for k in [h?5:0, h?9:5). smem row padded to 29 (gcd(29,32)=1).
__global__ void __launch_bounds__(256) gather_kernel(const float* __restrict__ pos,
                                                     const int* __restrict__ esrc,
                                                     int N) {
    __shared__ float sE[8][32][29];   // [warp][edge][rad16|sh9|pad]

    const int w = threadIdx.x >> 5;           // warp in block
    const int lane = threadIdx.x & 31;
    const int n = blockIdx.x * 8 + w;         // node
    if (n >= N) return;

    const int deg = g_cnt[n];
    const int nslot = min(deg, SLOTS);

    const float pdx = pos[3 * (size_t)n + 0];
    const float pdy = pos[3 * (size_t)n + 1];
    const float pdz = pos[3 * (size_t)n + 2];

    const int c = lane >> 1;
    const int h = lane & 1;
    const int k0 = h ? 5 : 0;
    const int nk = h ? 4 : 5;

    float acc[5] = {0.f, 0.f, 0.f, 0.f, 0.f};

    for (int base = 0; base < nslot; base += 32) {
        const int cnt = min(nslot - base, 32);
        float rad[CRAD], sh[SHD];
        if (lane < cnt) {
            const int e = g_eid[(size_t)n * SLOTS + base + lane];
            const int s = esrc[e];
            const float vx = pos[3 * (size_t)s + 0] - pdx;
            const float vy = pos[3 * (size_t)s + 1] - pdy;
            const float vz = pos[3 * (size_t)s + 2] - pdz;
            edge_geom(vx, vy, vz, rad, sh);
            #pragma unroll
            for (int q = 0; q < CRAD; q++) sE[w][lane][q] = rad[q];
            #pragma unroll
            for (int q = 0; q < SHD; q++) sE[w][lane][CRAD + q] = sh[q];
        }
        __syncwarp();
        for (int e2 = 0; e2 < cnt; e2++) {
            const float r = sE[w][e2][c];
            #pragma unroll
            for (int m = 0; m < 5; m++) {
                if (m < nk) acc[m] = fmaf(r, sE[w][e2][CRAD + k0 + m], acc[m]);
            }
        }
        __syncwarp();
    }

    float* dst = g_deg + (size_t)n * FEAT + 9 * c + k0;
    #pragma unroll
    for (int m = 0; m < 5; m++) {
        if (m < nk) dst[m] = acc[m] * INV_SQRT_DEG;
    }
}

// ---------------- kernel D: overflow fixup (rare; v4 reductions) ----------------
__global__ void fixup_kernel(const float* __restrict__ pos,
                             const int* __restrict__ esrc,
                             const int* __restrict__ edst) {
    const int novf = min(g_ovfcnt, OVF_CAP);
    for (int i = threadIdx.x + blockIdx.x * blockDim.x; i < novf; i += blockDim.x * gridDim.x) {
        const int e = g_ovf[i];
        const int s = esrc[e];
        const int d = edst[e];
        const float vx = pos[3 * (size_t)s + 0] - pos[3 * (size_t)d + 0];
        const float vy = pos[3 * (size_t)s + 1] - pos[3 * (size_t)d + 1];
        const float vz = pos[3 * (size_t)s + 2] - pos[3 * (size_t)d + 2];
        float rad[CRAD], sh[SHD];
        edge_geom(vx, vy, vz, rad, sh);
        float* base = g_deg + (size_t)d * FEAT;
        #pragma unroll
        for (int g = 0; g < FEAT / 4; g++) {
            const float e0 = rad[(4 * g + 0) / SHD] * sh[(4 * g + 0) % SHD] * INV_SQRT_DEG;
            const float e1 = rad[(4 * g + 1) / SHD] * sh[(4 * g + 1) % SHD] * INV_SQRT_DEG;
            const float e2 = rad[(4 * g + 2) / SHD] * sh[(4 * g + 2) % SHD] * INV_SQRT_DEG;
            const float e3 = rad[(4 * g + 3) / SHD] * sh[(4 * g + 3) % SHD] * INV_SQRT_DEG;
            asm volatile("red.global.add.v4.f32 [%0], {%1, %2, %3, %4};"
                         :: "l"(base + 4 * g), "f"(e0), "f"(e1), "f"(e2), "f"(e3)
                         : "memory");
        }
    }
}

// ---------------- kernel E: node head + graph reduction ----------------
__global__ void __launch_bounds__(288) node_kernel(const float* __restrict__ atab,
                                                   const int* __restrict__ natom,
                                                   const float* __restrict__ Wh1,
                                                   const float* __restrict__ bh1,
                                                   const float* __restrict__ Wh2,
                                                   const float* __restrict__ bh2,
                                                   const int* __restrict__ batch,
                                                   float* __restrict__ out,
                                                   int N) {
    __shared__ float sNF[32][FEAT];

    const int t = threadIdx.x;
    const int tx = t % 36;          // j0 = 4*tx
    const int ty = t / 36;          // 0..7
    const int nb = blockIdx.x * 32;

    for (int idx = t; idx < 32 * FEAT; idx += 288) {
        const int n = idx / FEAT;
        const int k = idx - n * FEAT;
        const int gn = nb + n;
        float v = 0.0f;
        if (gn < N) {
            v = atab[(size_t)natom[gn] * FEAT + k] + g_deg[(size_t)gn * FEAT + k];
        }
        sNF[n][k] = v;
    }
    __syncthreads();

    unsigned long long acc01[4], acc23[4];
    #pragma unroll
    for (int nn = 0; nn < 4; nn++) { acc01[nn] = 0ULL; acc23[nn] = 0ULL; }

    const int j0 = 4 * tx;
    for (int k = 0; k < FEAT; k++) {
        const float4 w = *reinterpret_cast<const float4*>(Wh1 + (size_t)k * FEAT + j0);
        const unsigned long long w01 = pk2(w.x, w.y);
        const unsigned long long w23 = pk2(w.z, w.w);
        #pragma unroll
        for (int nn = 0; nn < 4; nn++) {
            const float v = sNF[ty + 8 * nn][k];
            const unsigned long long vv = pk2(v, v);
            fma2(acc01[nn], vv, w01);
            fma2(acc23[nn], vv, w23);
        }
    }

    const float4 b4 = *reinterpret_cast<const float4*>(bh1 + j0);
    const float4 w2 = *reinterpret_cast<const float4*>(Wh2 + j0);
    const float bias2 = bh2[0];

    #pragma unroll
    for (int nn = 0; nn < 4; nn++) {
        const int gn = nb + ty + 8 * nn;
        if (gn >= N) continue;
        float a0, a1, a2, a3;
        unpk2(acc01[nn], a0, a1);
        unpk2(acc23[nn], a2, a3);
        float p = silu_f(a0 + b4.x) * w2.x
                + silu_f(a1 + b4.y) * w2.y
                + silu_f(a2 + b4.z) * w2.z
                + silu_f(a3 + b4.w) * w2.w;
        if (tx == 0) p += bias2;
        atomicAdd(out + batch[gn], p * INV_SQRT_NODES);
    }
}

// ---------------- launcher ----------------
extern "C" void kernel_launch(void* const* d_in, const int* in_sizes, int n_in,
                              void* d_out, int out_size) {
    const float* pos  = (const float*)d_in[0];
    const float* atab = (const float*)d_in[1];
    const float* W1   = (const float*)d_in[2];
    const float* b1   = (const float*)d_in[3];
    const float* W2   = (const float*)d_in[4];
    const float* b2   = (const float*)d_in[5];
    const float* W3   = (const float*)d_in[6];
    const float* Wh1  = (const float*)d_in[7];
    const float* bh1  = (const float*)d_in[8];
    const float* Wh2  = (const float*)d_in[9];
    const float* bh2  = (const float*)d_in[10];
    const int* natom  = (const int*)d_in[11];
    const int* esrc   = (const int*)d_in[12];
    const int* edst   = (const int*)d_in[13];
    const int* batch  = (const int*)d_in[14];
    float* out = (float*)d_out;

    const int N = in_sizes[11];
    const int E = in_sizes[12];
    const int G = out_size;

    // A: zero counters + output
    zero_kernel<<<(NNODES + 255) / 256, 256>>>(out, G);

    // B: radial table + edge bucketing (independent halves, one launch)
    const int scatter_blocks = (E + 255) / 256;
    fat_kernel<<<(TBL + 1) + scatter_blocks, 256>>>(W1, b1, W2, b2, W3, edst, E);

    // C: warp-per-node gather (writes g_deg fully; no zeroing needed)
    gather_kernel<<<(N + 7) / 8, 256>>>(pos, esrc, N);

    // D: overflow fixup (rare)
    fixup_kernel<<<4, 256>>>(pos, esrc, edst);

    // E: node head + graph reduction
    node_kernel<<<(N + 31) / 32, 288>>>(atab, natom, Wh1, bh1, Wh2, bh2, batch, out, N);
}